// round 6
// baseline (speedup 1.0000x reference)
#include <cuda_runtime.h>
#include <stdint.h>

// out[e,f] = (node_src[src[e],f] + off_src[e,f]) * (node_tgt[tgt[e],f] + off_tgt[e,f])
// F = 256 floats, E = 300000, N = 50000, edge_ids int32.
//
// HBM-bound. Compulsory traffic: 922 MB streams + ~102 MB node first-touch.
// Measured gather hit rate was only ~51% (L2 thrashed by the streams), so we
// reorder edge PROCESSING order by src-id bucket (counting sort, recomputed
// every launch -> graph-safe, deterministic output since out[e] is keyed by
// original edge id). Streams stay evict-first.

#define MAXE      300000
#define NBUCKETS  512
#define BSHIFT    7        // bucket = src_id >> 7 (ids < 65536)

__device__ int g_hist[NBUCKETS];
__device__ int g_base[NBUCKETS];
__device__ int g_perm[MAXE];

// ---------- sort passes ----------
__global__ void zero_hist_kernel() {
    if (threadIdx.x < NBUCKETS) g_hist[threadIdx.x] = 0;
}

__global__ void hist_kernel(const int* __restrict__ src_ids, int E) {
    int e = blockIdx.x * blockDim.x + threadIdx.x;
    if (e < E) atomicAdd(&g_hist[((unsigned)src_ids[e]) >> BSHIFT], 1);
}

__global__ void scan_kernel() {
    __shared__ int sh[NBUCKETS];
    int i = threadIdx.x;
    int h = g_hist[i];
    sh[i] = h;
    __syncthreads();
    // Hillis-Steele inclusive scan
    for (int off = 1; off < NBUCKETS; off <<= 1) {
        int v = (i >= off) ? sh[i - off] : 0;
        __syncthreads();
        sh[i] += v;
        __syncthreads();
    }
    g_base[i] = sh[i] - h;  // exclusive
}

__global__ void scatter_kernel(const int* __restrict__ src_ids, int E) {
    int e = blockIdx.x * blockDim.x + threadIdx.x;
    if (e < E) {
        int b = ((unsigned)src_ids[e]) >> BSHIFT;
        int pos = atomicAdd(&g_base[b], 1);
        g_perm[pos] = e;
    }
}

// ---------- main kernel: 1 warp per edge, 8 floats per thread ----------
__global__ __launch_bounds__(256) void node_to_edge_perm_kernel(
    const float4* __restrict__ node_src,   // [N, 64] as float4
    const float4* __restrict__ node_tgt,
    const int* __restrict__ edge_src_ids,  // [E]
    const int* __restrict__ edge_tgt_ids,  // [E]
    const float4* __restrict__ off_src,    // [E, 64]
    const float4* __restrict__ off_tgt,
    float4* __restrict__ out,              // [E, 64]
    int E)
{
    int warp = (blockIdx.x * blockDim.x + threadIdx.x) >> 5;
    if (warp >= E) return;
    int lane = threadIdx.x & 31;

    int e = g_perm[warp];                        // warp-uniform broadcast

    long long s = (long long)edge_src_ids[e];
    long long t = (long long)edge_tgt_ids[e];

    long long rowq = (long long)e * 64 + lane * 2;  // float4 index in edge row
    long long sq   = s * 64 + lane * 2;
    long long tq   = t * 64 + lane * 2;

    float4 a0 = __ldg(&node_src[sq]);
    float4 a1 = __ldg(&node_src[sq + 1]);
    float4 c0 = __ldg(&node_tgt[tq]);
    float4 c1 = __ldg(&node_tgt[tq + 1]);

    float4 b0 = __ldcs(&off_src[rowq]);
    float4 b1 = __ldcs(&off_src[rowq + 1]);
    float4 d0 = __ldcs(&off_tgt[rowq]);
    float4 d1 = __ldcs(&off_tgt[rowq + 1]);

    float4 r0, r1;
    r0.x = (a0.x + b0.x) * (c0.x + d0.x);
    r0.y = (a0.y + b0.y) * (c0.y + d0.y);
    r0.z = (a0.z + b0.z) * (c0.z + d0.z);
    r0.w = (a0.w + b0.w) * (c0.w + d0.w);
    r1.x = (a1.x + b1.x) * (c1.x + d1.x);
    r1.y = (a1.y + b1.y) * (c1.y + d1.y);
    r1.z = (a1.z + b1.z) * (c1.z + d1.z);
    r1.w = (a1.w + b1.w) * (c1.w + d1.w);

    __stcs(&out[rowq], r0);
    __stcs(&out[rowq + 1], r1);
}

// ---------- fallback (no perm) for unexpected E ----------
__global__ __launch_bounds__(256) void node_to_edge_direct_kernel(
    const float4* __restrict__ node_src,
    const float4* __restrict__ node_tgt,
    const int* __restrict__ edge_src_ids,
    const int* __restrict__ edge_tgt_ids,
    const float4* __restrict__ off_src,
    const float4* __restrict__ off_tgt,
    float4* __restrict__ out,
    long long total4)
{
    long long idx = (long long)blockIdx.x * blockDim.x + threadIdx.x;
    if (idx >= total4) return;
    long long e = idx >> 6;
    int f4 = (int)(idx & 63);
    long long s = (long long)edge_src_ids[e];
    long long t = (long long)edge_tgt_ids[e];
    float4 a = __ldg(&node_src[s * 64 + f4]);
    float4 c = __ldg(&node_tgt[t * 64 + f4]);
    float4 b = __ldcs(&off_src[idx]);
    float4 d = __ldcs(&off_tgt[idx]);
    float4 r;
    r.x = (a.x + b.x) * (c.x + d.x);
    r.y = (a.y + b.y) * (c.y + d.y);
    r.z = (a.z + b.z) * (c.z + d.z);
    r.w = (a.w + b.w) * (c.w + d.w);
    __stcs(&out[idx], r);
}

extern "C" void kernel_launch(void* const* d_in, const int* in_sizes, int n_in,
                              void* d_out, int out_size) {
    // 0: node_src_feats [N,256] f32   1: node_tgt_feats [N,256] f32
    // 2: edge_ids [2,E] int32         3: off_edge_src [E,256] f32
    // 4: off_edge_tgt [E,256] f32
    const float4* node_src = (const float4*)d_in[0];
    const float4* node_tgt = (const float4*)d_in[1];
    const int*    edge_ids = (const int*)d_in[2];
    const float4* off_src  = (const float4*)d_in[3];
    const float4* off_tgt  = (const float4*)d_in[4];
    float4*       out      = (float4*)d_out;

    int E = in_sizes[2] / 2;
    const int* src_ids = edge_ids;
    const int* tgt_ids = edge_ids + E;

    if (E <= MAXE) {
        int thr = 256;
        int blks = (E + thr - 1) / thr;
        zero_hist_kernel<<<1, NBUCKETS>>>();
        hist_kernel<<<blks, thr>>>(src_ids, E);
        scan_kernel<<<1, NBUCKETS>>>();
        scatter_kernel<<<blks, thr>>>(src_ids, E);

        long long warps = E;                       // 1 warp per edge
        long long threads_total = warps * 32;
        long long mblocks = (threads_total + 255) / 256;
        node_to_edge_perm_kernel<<<(unsigned)mblocks, 256>>>(
            node_src, node_tgt, src_ids, tgt_ids, off_src, off_tgt, out, E);
    } else {
        long long total4 = (long long)E * 64;
        long long blocks = (total4 + 255) / 256;
        node_to_edge_direct_kernel<<<(unsigned)blocks, 256>>>(
            node_src, node_tgt, src_ids, tgt_ids, off_src, off_tgt, out, total4);
    }
}

// round 7
// speedup vs baseline: 1.4643x; 1.4643x over previous
#include <cuda_runtime.h>
#include <stdint.h>

// out[e,f] = (node_src[src[e],f] + off_src[e,f]) * (node_tgt[tgt[e],f] + off_tgt[e,f])
// F = 256 floats, E = 300000, N = 50000, edge_ids int32. HBM-bound.
//
// Strategy: process edges bucketed by src-id (cheap block-aggregated counting
// sort, recomputed every launch -> graph-safe; output keyed by original edge
// id -> deterministic). Node gathers then hit L2; offset streams + output use
// evict-first so they don't thrash the node tables.

#define MAXE      300000
#define NBUCKETS  512
#define BSHIFT    7        // bucket = src_id >> 7
#define SORT_BLOCKS 148

__device__ int g_hist[NBUCKETS];
__device__ int g_base[NBUCKETS];
__device__ int g_perm[MAXE];

// ---------- pass 0: zero ----------
__global__ void zero_hist_kernel() {
    if (threadIdx.x < NBUCKETS) g_hist[threadIdx.x] = 0;
}

// ---------- pass 1: block-aggregated histogram ----------
__global__ __launch_bounds__(256) void hist_kernel(const int* __restrict__ src_ids, int E) {
    __shared__ int h[NBUCKETS];
    for (int i = threadIdx.x; i < NBUCKETS; i += blockDim.x) h[i] = 0;
    __syncthreads();
    for (int e = blockIdx.x * blockDim.x + threadIdx.x; e < E;
         e += gridDim.x * blockDim.x)
        atomicAdd(&h[((unsigned)src_ids[e]) >> BSHIFT], 1);
    __syncthreads();
    for (int i = threadIdx.x; i < NBUCKETS; i += blockDim.x)
        if (h[i]) atomicAdd(&g_hist[i], h[i]);
}

// ---------- pass 2: exclusive scan over 512 bins ----------
__global__ void scan_kernel() {
    __shared__ int sh[NBUCKETS];
    int i = threadIdx.x;
    int h = g_hist[i];
    sh[i] = h;
    __syncthreads();
    for (int off = 1; off < NBUCKETS; off <<= 1) {
        int v = (i >= off) ? sh[i - off] : 0;
        __syncthreads();
        sh[i] += v;
        __syncthreads();
    }
    g_base[i] = sh[i] - h;  // exclusive prefix
}

// ---------- pass 3: block-range-claiming scatter ----------
__global__ __launch_bounds__(256) void scatter_kernel(const int* __restrict__ src_ids,
                                                      int E, int per_block) {
    __shared__ int cnt[NBUCKETS];
    __shared__ int base[NBUCKETS];
    int start = blockIdx.x * per_block;
    int end   = min(start + per_block, E);
    if (start >= E) return;

    for (int i = threadIdx.x; i < NBUCKETS; i += blockDim.x) cnt[i] = 0;
    __syncthreads();
    for (int e = start + threadIdx.x; e < end; e += blockDim.x)
        atomicAdd(&cnt[((unsigned)src_ids[e]) >> BSHIFT], 1);
    __syncthreads();
    // Claim a contiguous range per bucket for this block (148-deep contention).
    for (int i = threadIdx.x; i < NBUCKETS; i += blockDim.x) {
        int c = cnt[i];
        base[i] = c ? atomicAdd(&g_base[i], c) : 0;
    }
    __syncthreads();
    for (int i = threadIdx.x; i < NBUCKETS; i += blockDim.x) cnt[i] = 0;
    __syncthreads();
    for (int e = start + threadIdx.x; e < end; e += blockDim.x) {
        int b = ((unsigned)src_ids[e]) >> BSHIFT;
        int p = base[b] + atomicAdd(&cnt[b], 1);
        g_perm[p] = e;
    }
}

// ---------- main: 1 warp per edge, 8 floats per thread ----------
__global__ __launch_bounds__(256) void node_to_edge_perm_kernel(
    const float4* __restrict__ node_src,   // [N, 64] as float4
    const float4* __restrict__ node_tgt,
    const int* __restrict__ edge_src_ids,
    const int* __restrict__ edge_tgt_ids,
    const float4* __restrict__ off_src,    // [E, 64]
    const float4* __restrict__ off_tgt,
    float4* __restrict__ out,              // [E, 64]
    int E)
{
    int warp = (blockIdx.x * blockDim.x + threadIdx.x) >> 5;
    if (warp >= E) return;
    int lane = threadIdx.x & 31;

    int e = g_perm[warp];  // warp-uniform broadcast

    long long s = (long long)edge_src_ids[e];
    long long t = (long long)edge_tgt_ids[e];

    long long rowq = (long long)e * 64 + lane * 2;
    long long sq   = s * 64 + lane * 2;
    long long tq   = t * 64 + lane * 2;

    float4 a0 = __ldg(&node_src[sq]);
    float4 a1 = __ldg(&node_src[sq + 1]);
    float4 c0 = __ldg(&node_tgt[tq]);
    float4 c1 = __ldg(&node_tgt[tq + 1]);

    float4 b0 = __ldcs(&off_src[rowq]);
    float4 b1 = __ldcs(&off_src[rowq + 1]);
    float4 d0 = __ldcs(&off_tgt[rowq]);
    float4 d1 = __ldcs(&off_tgt[rowq + 1]);

    float4 r0, r1;
    r0.x = (a0.x + b0.x) * (c0.x + d0.x);
    r0.y = (a0.y + b0.y) * (c0.y + d0.y);
    r0.z = (a0.z + b0.z) * (c0.z + d0.z);
    r0.w = (a0.w + b0.w) * (c0.w + d0.w);
    r1.x = (a1.x + b1.x) * (c1.x + d1.x);
    r1.y = (a1.y + b1.y) * (c1.y + d1.y);
    r1.z = (a1.z + b1.z) * (c1.z + d1.z);
    r1.w = (a1.w + b1.w) * (c1.w + d1.w);

    __stcs(&out[rowq], r0);
    __stcs(&out[rowq + 1], r1);
}

// ---------- fallback (no perm) for unexpected E ----------
__global__ __launch_bounds__(256) void node_to_edge_direct_kernel(
    const float4* __restrict__ node_src,
    const float4* __restrict__ node_tgt,
    const int* __restrict__ edge_src_ids,
    const int* __restrict__ edge_tgt_ids,
    const float4* __restrict__ off_src,
    const float4* __restrict__ off_tgt,
    float4* __restrict__ out,
    long long total4)
{
    long long idx = (long long)blockIdx.x * blockDim.x + threadIdx.x;
    if (idx >= total4) return;
    long long e = idx >> 6;
    int f4 = (int)(idx & 63);
    long long s = (long long)edge_src_ids[e];
    long long t = (long long)edge_tgt_ids[e];
    float4 a = __ldg(&node_src[s * 64 + f4]);
    float4 c = __ldg(&node_tgt[t * 64 + f4]);
    float4 b = __ldcs(&off_src[idx]);
    float4 d = __ldcs(&off_tgt[idx]);
    float4 r;
    r.x = (a.x + b.x) * (c.x + d.x);
    r.y = (a.y + b.y) * (c.y + d.y);
    r.z = (a.z + b.z) * (c.z + d.z);
    r.w = (a.w + b.w) * (c.w + d.w);
    __stcs(&out[idx], r);
}

extern "C" void kernel_launch(void* const* d_in, const int* in_sizes, int n_in,
                              void* d_out, int out_size) {
    // 0: node_src_feats [N,256] f32   1: node_tgt_feats [N,256] f32
    // 2: edge_ids [2,E] int32         3: off_edge_src [E,256] f32
    // 4: off_edge_tgt [E,256] f32
    const float4* node_src = (const float4*)d_in[0];
    const float4* node_tgt = (const float4*)d_in[1];
    const int*    edge_ids = (const int*)d_in[2];
    const float4* off_src  = (const float4*)d_in[3];
    const float4* off_tgt  = (const float4*)d_in[4];
    float4*       out      = (float4*)d_out;

    int E = in_sizes[2] / 2;
    const int* src_ids = edge_ids;
    const int* tgt_ids = edge_ids + E;

    if (E <= MAXE) {
        zero_hist_kernel<<<1, NBUCKETS>>>();
        hist_kernel<<<SORT_BLOCKS, 256>>>(src_ids, E);
        scan_kernel<<<1, NBUCKETS>>>();
        int per_block = (E + SORT_BLOCKS - 1) / SORT_BLOCKS;
        scatter_kernel<<<SORT_BLOCKS, 256>>>(src_ids, E, per_block);

        long long threads_total = (long long)E * 32;  // 1 warp per edge
        long long mblocks = (threads_total + 255) / 256;
        node_to_edge_perm_kernel<<<(unsigned)mblocks, 256>>>(
            node_src, node_tgt, src_ids, tgt_ids, off_src, off_tgt, out, E);
    } else {
        long long total4 = (long long)E * 64;
        long long blocks = (total4 + 255) / 256;
        node_to_edge_direct_kernel<<<(unsigned)blocks, 256>>>(
            node_src, node_tgt, src_ids, tgt_ids, off_src, off_tgt, out, total4);
    }
}

// round 8
// speedup vs baseline: 1.6178x; 1.1048x over previous
#include <cuda_runtime.h>
#include <stdint.h>

// out[e,f] = (node_src[src[e],f] + off_src[e,f]) * (node_tgt[tgt[e],f] + off_tgt[e,f])
// F = 256 floats, E = 300000, N = 50000, edge_ids int32. HBM-bound.
//
// Feature-phase slicing: 4 phases x 64 columns. Phase p handles columns
// [64p, 64p+64) for ALL edges, ordered by blockIdx so phases execute ~in
// sequence. Per-phase gathered node working set = 2 x 12.8 MB = 25.6 MB,
// fits in L2 despite the streaming flood -> gathers become L2 hits after
// first touch. Streams + output use evict-first (.cs): zero reuse.
// Each thread: 8 floats (2 float4 per operand).

#define NPHASE 4
#define GP     8   // 8-float groups per phase per row (8*8=64 cols)

__global__ __launch_bounds__(256) void node_to_edge_phased_kernel(
    const float4* __restrict__ node_src,   // [N, 64] as float4
    const float4* __restrict__ node_tgt,
    const int* __restrict__ edge_src_ids,  // [E]
    const int* __restrict__ edge_tgt_ids,  // [E]
    const float4* __restrict__ off_src,    // [E, 64]
    const float4* __restrict__ off_tgt,
    float4* __restrict__ out,              // [E, 64]
    unsigned E,
    unsigned per_phase)                    // E * GP
{
    unsigned gid = blockIdx.x * blockDim.x + threadIdx.x;
    unsigned phase = gid / per_phase;
    if (phase >= NPHASE) return;
    unsigned rem = gid - phase * per_phase;
    unsigned e = rem / GP;          // edge id (original order)
    unsigned g = rem - e * GP;      // group within phase
    if (e >= E) return;
    unsigned grp = phase * GP + g;  // 8-float group within row, 0..31

    long long s = (long long)edge_src_ids[e];
    long long t = (long long)edge_tgt_ids[e];

    long long q  = (long long)e * 64 + grp * 2;   // float4 index in edge row
    long long sq = s * 64 + grp * 2;
    long long tq = t * 64 + grp * 2;

    // Gathered node slices (25.6 MB/phase working set): default caching.
    float4 a0 = __ldg(&node_src[sq]);
    float4 a1 = __ldg(&node_src[sq + 1]);
    float4 c0 = __ldg(&node_tgt[tq]);
    float4 c1 = __ldg(&node_tgt[tq + 1]);

    // Single-use streams: evict-first.
    float4 b0 = __ldcs(&off_src[q]);
    float4 b1 = __ldcs(&off_src[q + 1]);
    float4 d0 = __ldcs(&off_tgt[q]);
    float4 d1 = __ldcs(&off_tgt[q + 1]);

    float4 r0, r1;
    r0.x = (a0.x + b0.x) * (c0.x + d0.x);
    r0.y = (a0.y + b0.y) * (c0.y + d0.y);
    r0.z = (a0.z + b0.z) * (c0.z + d0.z);
    r0.w = (a0.w + b0.w) * (c0.w + d0.w);
    r1.x = (a1.x + b1.x) * (c1.x + d1.x);
    r1.y = (a1.y + b1.y) * (c1.y + d1.y);
    r1.z = (a1.z + b1.z) * (c1.z + d1.z);
    r1.w = (a1.w + b1.w) * (c1.w + d1.w);

    __stcs(&out[q], r0);
    __stcs(&out[q + 1], r1);
}

extern "C" void kernel_launch(void* const* d_in, const int* in_sizes, int n_in,
                              void* d_out, int out_size) {
    // 0: node_src_feats [N,256] f32   1: node_tgt_feats [N,256] f32
    // 2: edge_ids [2,E] int32         3: off_edge_src [E,256] f32
    // 4: off_edge_tgt [E,256] f32
    const float4* node_src = (const float4*)d_in[0];
    const float4* node_tgt = (const float4*)d_in[1];
    const int*    edge_ids = (const int*)d_in[2];
    const float4* off_src  = (const float4*)d_in[3];
    const float4* off_tgt  = (const float4*)d_in[4];
    float4*       out      = (float4*)d_out;

    unsigned E = (unsigned)(in_sizes[2] / 2);
    const int* src_ids = edge_ids;
    const int* tgt_ids = edge_ids + E;

    unsigned per_phase = E * GP;                 // threads per phase
    unsigned long long total = (unsigned long long)per_phase * NPHASE;
    unsigned blocks = (unsigned)((total + 255) / 256);

    node_to_edge_phased_kernel<<<blocks, 256>>>(
        node_src, node_tgt, src_ids, tgt_ids, off_src, off_tgt, out,
        E, per_phase);
}